// round 1
// baseline (speedup 1.0000x reference)
#include <cuda_runtime.h>
#include <math.h>

// Problem constants
#define BNUM 32
#define SEQ  2048
#define DIM  1024
#define HID  512
#define NTOK (BNUM * SEQ)   // 65536
#define MARGIN 50.0f        // exp(-50) ~ 2e-22, far below 1e-3 tolerance

// ---------------- scratch (device globals; no runtime allocation) ----------------
__device__ float d_H[(size_t)NTOK * HID];  // 128 MB: GELU(h) for selected tokens (compact rows)
__device__ float d_qk[DIM];                // key_w @ q
__device__ float d_xq[NTOK];               // x_row . qk
__device__ float d_g[NTOK];                // gate per token (selected only)
__device__ float d_dec[NTOK];              // decayed logits (-1e30 = excluded)
__device__ float d_w[NTOK];                // alpha * g per token
__device__ int   d_len[BNUM];              // valid lengths
__device__ int   d_idx[NTOK];              // selected token ids (compacted)
__device__ int   d_cnt;                    // number of selected tokens
__device__ int   d_mdtype;                 // 0=u8/bool, 1=int32, 2=float32

// ---------------- block reduce helper (blockDim == 256) ----------------
__device__ __forceinline__ float blk_reduce(float v, float* red, bool domax) {
    #pragma unroll
    for (int o = 16; o; o >>= 1) {
        float ov = __shfl_xor_sync(0xffffffffu, v, o);
        v = domax ? fmaxf(v, ov) : (v + ov);
    }
    int w = threadIdx.x >> 5;
    if ((threadIdx.x & 31) == 0) red[w] = v;
    __syncthreads();
    float r = (threadIdx.x < 8) ? red[threadIdx.x] : (domax ? -1e30f : 0.0f);
    if (threadIdx.x < 32) {
        #pragma unroll
        for (int o = 4; o; o >>= 1) {
            float orr = __shfl_xor_sync(0xffffffffu, r, o);
            r = domax ? fmaxf(r, orr) : (r + orr);
        }
        if (threadIdx.x == 0) red[0] = r;
    }
    __syncthreads();
    float out = red[0];
    __syncthreads();   // make red reusable by caller
    return out;
}

// ---------------- K0: detect mask dtype + zero counter ----------------
// Reads only the first 65536 bytes: in-bounds for u8 (64KB), i32 (256KB), f32 (256KB).
// i32 0/1 LE: nonzero bytes only at p%4==0. f32 1.0f LE [00,00,80,3F]: only p%4 in {2,3}.
// u8 bool: padding runs (len up to 1024) hit all residues.
__global__ void k_detect(const unsigned char* mb) {
    __shared__ int c0s, c3s;
    if (threadIdx.x == 0) { c0s = 0; c3s = 0; d_cnt = 0; }
    __syncthreads();
    int c0 = 0, c3 = 0;
    for (int i = threadIdx.x; i < NTOK; i += blockDim.x) {
        if (mb[i]) { int r = i & 3; if (r == 0) c0++; else if (r == 3) c3++; }
    }
    atomicAdd(&c0s, c0); atomicAdd(&c3s, c3);
    __syncthreads();
    if (threadIdx.x == 0) {
        int f = 0;
        if (c0s > 0 && c3s == 0) f = 1;        // int32
        else if (c0s == 0 && c3s > 0) f = 2;   // float32
        d_mdtype = f;                           // mixed (or all-zero) -> u8
    }
}

// ---------------- K1: per-row valid lengths ----------------
__global__ void k_len(const void* mask) {
    int b = blockIdx.x, tid = threadIdx.x;
    __shared__ int cs;
    if (tid == 0) cs = 0;
    __syncthreads();
    int c = 0, f = d_mdtype;
    if (f == 0) {
        const unsigned char* m = (const unsigned char*)mask;
        for (int s = tid; s < SEQ; s += blockDim.x) c += m[b * SEQ + s] ? 1 : 0;
    } else if (f == 1) {
        const int* m = (const int*)mask;
        for (int s = tid; s < SEQ; s += blockDim.x) c += m[b * SEQ + s] ? 1 : 0;
    } else {
        const float* m = (const float*)mask;
        for (int s = tid; s < SEQ; s += blockDim.x) c += (m[b * SEQ + s] != 0.0f) ? 1 : 0;
    }
    atomicAdd(&cs, c);
    __syncthreads();
    if (tid == 0) d_len[b] = SEQ - cs;
}

// ---------------- K2: qk = key_w @ q  (row-dot per block) ----------------
__global__ void k_qk(const float* __restrict__ kw, const float* __restrict__ q) {
    __shared__ float red[8];
    int d = blockIdx.x, tid = threadIdx.x;
    const float* row = kw + (size_t)d * DIM;
    int e = tid * 4;   // 256 threads * 4 = 1024 exactly
    float4 a = *(const float4*)(row + e);
    float4 b = *(const float4*)(q + e);
    float s = a.x * b.x + a.y * b.y + a.z * b.z + a.w * b.w;
    s = blk_reduce(s, red, false);
    if (tid == 0) d_qk[d] = s;
}

// ---------------- K3: xq[t] = x_row . qk  (one warp per token) ----------------
__global__ void k_xq(const float* __restrict__ X) {
    __shared__ float qs[DIM];
    int tid = threadIdx.x;
    for (int i = tid; i < DIM; i += 256) qs[i] = d_qk[i];
    __syncthreads();
    int t = blockIdx.x * 8 + (tid >> 5);
    int lane = tid & 31;
    const float* xr = X + (size_t)t * DIM;
    float s = 0.0f;
    #pragma unroll
    for (int i = 0; i < 8; i++) {
        float4 a = *(const float4*)(xr + lane * 4 + i * 128);
        float4 b = *(const float4*)(qs + lane * 4 + i * 128);
        s += a.x * b.x + a.y * b.y + a.z * b.z + a.w * b.w;
    }
    #pragma unroll
    for (int o = 16; o; o >>= 1) s += __shfl_xor_sync(0xffffffffu, s, o);
    if (lane == 0) d_xq[t] = s;
}

// ---------------- K4: rigorous-bound token selection ----------------
// g in (0,1) => g*xq in [min(xq,0), max(xq,0)]. Select s iff upper(s) >= max_s' lower(s') - MARGIN.
__global__ void k_select(const float* __restrict__ dlam) {
    __shared__ float red[8];
    int b = blockIdx.x, tid = threadIdx.x;
    int L = d_len[b];
    float lam = log1pf(expf(dlam[0]));   // softplus
    float lmax = -1e30f;
    for (int s = tid; s < SEQ; s += 256) {
        if (s < L) {
            float xq = d_xq[b * SEQ + s];
            float l = fminf(xq, 0.0f) * 0.03125f - lam * (float)(L - 1 - s);
            lmax = fmaxf(lmax, l);
        }
    }
    lmax = blk_reduce(lmax, red, true);
    float thr = lmax - MARGIN;
    for (int s = tid; s < SEQ; s += 256) {
        int t = b * SEQ + s;
        d_dec[t] = -1e30f;
        if (s < L) {
            float xq = d_xq[t];
            float u = fmaxf(xq, 0.0f) * 0.03125f - lam * (float)(L - 1 - s);
            if (u >= thr) { int p = atomicAdd(&d_cnt, 1); d_idx[p] = t; }
        }
    }
}

// ---------------- K5: gathered GEMM  H = GELU(X[sel] @ W1 + b1) ----------------
#define BM 64
#define BN 64
#define BK 16
__global__ __launch_bounds__(256) void k_gemm(const float* __restrict__ X,
                                              const float* __restrict__ W1,
                                              const float* __restrict__ b1) {
    int cnt = d_cnt;
    int row0 = blockIdx.x * BM;
    if (row0 >= cnt) return;
    int n0 = blockIdx.y * BN;
    __shared__ float Xs[BK][BM];
    __shared__ float Ws[BK][BN];
    __shared__ int tok[BM];
    int tid = threadIdx.x;
    if (tid < BM) { int r = row0 + tid; tok[tid] = d_idx[(r < cnt) ? r : 0]; }
    __syncthreads();

    float acc[4][4];
    #pragma unroll
    for (int i = 0; i < 4; i++)
        #pragma unroll
        for (int j = 0; j < 4; j++) acc[i][j] = 0.0f;

    int lxm = tid >> 2, lxk = (tid & 3) * 4;     // X tile: 64 rows x 16 cols, 1 float4/thread
    int lwk = tid >> 4, lwn = (tid & 15) * 4;    // W tile: 16 rows x 64 cols, 1 float4/thread
    int tm = tid >> 4, tn = tid & 15;            // 16x16 thread grid, 4x4 micro-tile
    const float* xr = X + (size_t)tok[lxm] * DIM + lxk;

    for (int k0 = 0; k0 < DIM; k0 += BK) {
        float4 v  = *(const float4*)(xr + k0);
        float4 wv = *(const float4*)(W1 + (size_t)(k0 + lwk) * HID + n0 + lwn);
        Xs[lxk + 0][lxm] = v.x; Xs[lxk + 1][lxm] = v.y;
        Xs[lxk + 2][lxm] = v.z; Xs[lxk + 3][lxm] = v.w;
        *(float4*)&Ws[lwk][lwn] = wv;
        __syncthreads();
        #pragma unroll
        for (int k = 0; k < BK; k++) {
            float a[4], bb[4];
            *(float4*)a  = *(const float4*)&Xs[k][tm * 4];
            *(float4*)bb = *(const float4*)&Ws[k][tn * 4];
            #pragma unroll
            for (int i = 0; i < 4; i++)
                #pragma unroll
                for (int j = 0; j < 4; j++) acc[i][j] += a[i] * bb[j];
        }
        __syncthreads();
    }
    // epilogue: +b1, exact GELU (erf), store compact rows
    float bv[4];
    *(float4*)bv = *(const float4*)(b1 + n0 + tn * 4);
    #pragma unroll
    for (int i = 0; i < 4; i++) {
        int r = row0 + tm * 4 + i;
        if (r < cnt) {
            float o[4];
            #pragma unroll
            for (int j = 0; j < 4; j++) {
                float h = acc[i][j] + bv[j];
                o[j] = 0.5f * h * (1.0f + erff(h * 0.70710678118654752f));
            }
            *(float4*)&d_H[(size_t)r * HID + n0 + tn * 4] = *(float4*)o;
        }
    }
}

// ---------------- K6: gate + decayed logit for selected tokens ----------------
__global__ void k_gate(const float* __restrict__ w2, const float* __restrict__ b2,
                       const float* __restrict__ dlam) {
    int i = blockIdx.x * 8 + (threadIdx.x >> 5);
    if (i >= d_cnt) return;
    int lane = threadIdx.x & 31;
    int t = d_idx[i];
    const float* h = d_H + (size_t)i * HID;
    float z = 0.0f;
    #pragma unroll
    for (int q2 = 0; q2 < 4; q2++) {
        float4 a = *(const float4*)(h + lane * 4 + q2 * 128);
        float4 b = *(const float4*)(w2 + lane * 4 + q2 * 128);
        z += a.x * b.x + a.y * b.y + a.z * b.z + a.w * b.w;
    }
    #pragma unroll
    for (int o = 16; o; o >>= 1) z += __shfl_xor_sync(0xffffffffu, z, o);
    if (lane == 0) {
        float g = 1.0f / (1.0f + expf(-(z + b2[0])));
        d_g[t] = g;
        int b = t >> 11, s = t & (SEQ - 1);
        int L = d_len[b];
        float lam = log1pf(expf(dlam[0]));
        d_dec[t] = g * d_xq[t] * 0.03125f - lam * (float)(L - 1 - s);
    }
}

// ---------------- K7: row softmax -> w = alpha * g ----------------
__global__ void k_softmax() {
    __shared__ float red[8];
    int b = blockIdx.x, tid = threadIdx.x;
    float v[8];
    float mx = -1e30f;
    #pragma unroll
    for (int q2 = 0; q2 < 8; q2++) {
        v[q2] = d_dec[b * SEQ + tid + q2 * 256];
        mx = fmaxf(mx, v[q2]);
    }
    mx = blk_reduce(mx, red, true);
    float p[8];
    float sm = 0.0f;
    #pragma unroll
    for (int q2 = 0; q2 < 8; q2++) {
        p[q2] = (v[q2] > -1e29f) ? expf(v[q2] - mx) : 0.0f;
        sm += p[q2];
    }
    sm = blk_reduce(sm, red, false);
    float inv = 1.0f / sm;
    #pragma unroll
    for (int q2 = 0; q2 < 8; q2++) {
        int t = b * SEQ + tid + q2 * 256;
        d_w[t] = (p[q2] > 0.0f) ? p[q2] * inv * d_g[t] : 0.0f;
    }
}

// ---------------- K8: scene[b,d] = sum_s w[b,s] * x[b,s,d] (skip zero prefix) --------
__global__ void k_scene(const float* __restrict__ X, float* __restrict__ out) {
    int b = blockIdx.y;
    int d = blockIdx.x * 128 + threadIdx.x;
    __shared__ float w[SEQ];
    __shared__ int slo_s;
    int L = d_len[b];
    if (threadIdx.x == 0) slo_s = L;
    __syncthreads();
    int slo = L;
    for (int s = threadIdx.x; s < SEQ; s += 128) {
        float wv = d_w[b * SEQ + s];
        w[s] = wv;
        if (wv != 0.0f && s < slo) slo = s;
    }
    atomicMin(&slo_s, slo);
    __syncthreads();
    const float* xb = X + (size_t)b * SEQ * DIM + d;
    float a0 = 0.0f, a1 = 0.0f, a2 = 0.0f, a3 = 0.0f;
    int s = slo_s;
    for (; s + 3 < L; s += 4) {
        a0 += w[s + 0] * xb[(size_t)(s + 0) * DIM];
        a1 += w[s + 1] * xb[(size_t)(s + 1) * DIM];
        a2 += w[s + 2] * xb[(size_t)(s + 2) * DIM];
        a3 += w[s + 3] * xb[(size_t)(s + 3) * DIM];
    }
    for (; s < L; s++) a0 += w[s] * xb[(size_t)s * DIM];
    out[b * DIM + d] = (a0 + a1) + (a2 + a3);
}

// ---------------- launch ----------------
extern "C" void kernel_launch(void* const* d_in, const int* in_sizes, int n_in,
                              void* d_out, int out_size) {
    (void)in_sizes; (void)n_in; (void)out_size;
    const float* X    = (const float*)d_in[0];
    const void*  mask = d_in[1];
    const float* gw1  = (const float*)d_in[2];
    const float* gb1  = (const float*)d_in[3];
    const float* gw2  = (const float*)d_in[4];
    const float* gb2  = (const float*)d_in[5];
    const float* dlam = (const float*)d_in[6];
    const float* q    = (const float*)d_in[7];
    const float* kw   = (const float*)d_in[8];
    // d_in[9] = key_b: constant softmax shift, provably drops out (masked exps underflow to 0)
    float* out = (float*)d_out;

    k_detect  <<<1, 256>>>((const unsigned char*)mask);
    k_len     <<<BNUM, 256>>>(mask);
    k_qk      <<<DIM, 256>>>(kw, q);
    k_xq      <<<NTOK / 8, 256>>>(X);
    k_select  <<<BNUM, 256>>>(dlam);
    k_gemm    <<<dim3(NTOK / BM, HID / BN), 256>>>(X, gw1, gb1);
    k_gate    <<<NTOK / 8, 256>>>(gw2, gb2, dlam);
    k_softmax <<<BNUM, 256>>>();
    k_scene   <<<dim3(DIM / 128, BNUM), 128>>>(X, out);
}

// round 2
// speedup vs baseline: 1.1231x; 1.1231x over previous
#include <cuda_runtime.h>
#include <math.h>

// Problem constants
#define BNUM 32
#define SEQ  2048
#define DIM  1024
#define HID  512
#define NTOK (BNUM * SEQ)   // 65536
#define MARGIN 20.0f        // dropped alpha mass < 2048*exp(-20) ~ 4e-6 << 1e-3 tol

// ---------------- scratch (device globals; no runtime allocation) ----------------
__device__ float d_H[(size_t)NTOK * HID];  // GELU(h) for selected tokens (compact rows)
__device__ float d_qk[DIM];                // key_w @ q
__device__ float d_xq[NTOK];               // x_row . qk
__device__ float d_g[NTOK];                // gate per token (selected only)
__device__ float d_dec[NTOK];              // decayed logits (-1e30 = excluded)
__device__ float d_w[NTOK];                // alpha * g per token
__device__ int   d_len[BNUM];              // valid lengths
__device__ int   d_idx[NTOK];              // selected token ids (compacted)
__device__ int   d_cnt;                    // number of selected tokens
__device__ int   d_mdtype;                 // 0=u8/bool, 1=int32, 2=float32

// ---------------- block reduce helper (blockDim == 256) ----------------
__device__ __forceinline__ float blk_reduce(float v, float* red, bool domax) {
    #pragma unroll
    for (int o = 16; o; o >>= 1) {
        float ov = __shfl_xor_sync(0xffffffffu, v, o);
        v = domax ? fmaxf(v, ov) : (v + ov);
    }
    int w = threadIdx.x >> 5;
    if ((threadIdx.x & 31) == 0) red[w] = v;
    __syncthreads();
    float r = (threadIdx.x < 8) ? red[threadIdx.x] : (domax ? -1e30f : 0.0f);
    if (threadIdx.x < 32) {
        #pragma unroll
        for (int o = 4; o; o >>= 1) {
            float orr = __shfl_xor_sync(0xffffffffu, r, o);
            r = domax ? fmaxf(r, orr) : (r + orr);
        }
        if (threadIdx.x == 0) red[0] = r;
    }
    __syncthreads();
    float out = red[0];
    __syncthreads();
    return out;
}

// ---------------- K0: detect mask dtype + zero counter ----------------
// Reads only first 65536 bytes (in-bounds for every candidate dtype).
// i32 0/1 LE: nonzero bytes only at p%4==0. f32 1.0f LE: only p%4 in {2,3}. u8: mixed.
__global__ void k_detect(const unsigned char* mb) {
    __shared__ int c0s, c3s;
    if (threadIdx.x == 0) { c0s = 0; c3s = 0; d_cnt = 0; }
    __syncthreads();
    int c0 = 0, c3 = 0;
    for (int i = threadIdx.x; i < NTOK; i += blockDim.x) {
        if (mb[i]) { int r = i & 3; if (r == 0) c0++; else if (r == 3) c3++; }
    }
    atomicAdd(&c0s, c0); atomicAdd(&c3s, c3);
    __syncthreads();
    if (threadIdx.x == 0) {
        int f = 0;
        if (c0s > 0 && c3s == 0) f = 1;        // int32
        else if (c0s == 0 && c3s > 0) f = 2;   // float32
        d_mdtype = f;
    }
}

// ---------------- K1: per-row valid lengths ----------------
__global__ void k_len(const void* mask) {
    int b = blockIdx.x, tid = threadIdx.x;
    __shared__ int cs;
    if (tid == 0) cs = 0;
    __syncthreads();
    int c = 0, f = d_mdtype;
    if (f == 0) {
        const unsigned char* m = (const unsigned char*)mask;
        for (int s = tid; s < SEQ; s += blockDim.x) c += m[b * SEQ + s] ? 1 : 0;
    } else if (f == 1) {
        const int* m = (const int*)mask;
        for (int s = tid; s < SEQ; s += blockDim.x) c += m[b * SEQ + s] ? 1 : 0;
    } else {
        const float* m = (const float*)mask;
        for (int s = tid; s < SEQ; s += blockDim.x) c += (m[b * SEQ + s] != 0.0f) ? 1 : 0;
    }
    atomicAdd(&cs, c);
    __syncthreads();
    if (tid == 0) d_len[b] = SEQ - cs;
}

// ---------------- K2: qk = key_w @ q ----------------
__global__ void k_qk(const float* __restrict__ kw, const float* __restrict__ q) {
    __shared__ float red[8];
    int d = blockIdx.x, tid = threadIdx.x;
    const float* row = kw + (size_t)d * DIM;
    int e = tid * 4;
    float4 a = *(const float4*)(row + e);
    float4 b = *(const float4*)(q + e);
    float s = a.x * b.x + a.y * b.y + a.z * b.z + a.w * b.w;
    s = blk_reduce(s, red, false);
    if (tid == 0) d_qk[d] = s;
}

// ---------------- K3: xq[t] = x_row . qk  (2 tokens per warp for MLP) ----------------
__global__ void k_xq(const float* __restrict__ X) {
    __shared__ float qs[DIM];
    int tid = threadIdx.x;
    for (int i = tid; i < DIM; i += 256) qs[i] = d_qk[i];
    __syncthreads();
    int w = tid >> 5, lane = tid & 31;
    int t0 = blockIdx.x * 16 + w;           // this warp handles t0 and t0+8
    const float* x0 = X + (size_t)t0 * DIM;
    const float* x1 = x0 + (size_t)8 * DIM;
    float s0 = 0.0f, s1 = 0.0f;
    #pragma unroll
    for (int i = 0; i < 8; i++) {
        float4 b  = *(const float4*)(qs + lane * 4 + i * 128);
        float4 a0 = *(const float4*)(x0 + lane * 4 + i * 128);
        float4 a1 = *(const float4*)(x1 + lane * 4 + i * 128);
        s0 += a0.x * b.x + a0.y * b.y + a0.z * b.z + a0.w * b.w;
        s1 += a1.x * b.x + a1.y * b.y + a1.z * b.z + a1.w * b.w;
    }
    #pragma unroll
    for (int o = 16; o; o >>= 1) {
        s0 += __shfl_xor_sync(0xffffffffu, s0, o);
        s1 += __shfl_xor_sync(0xffffffffu, s1, o);
    }
    if (lane == 0) { d_xq[t0] = s0; d_xq[t0 + 8] = s1; }
}

// ---------------- K4: rigorous-bound token selection ----------------
// g in (0,1) => g*xq in [min(xq,0), max(xq,0)]. Select s iff upper(s) >= max lower - MARGIN.
__global__ void k_select(const float* __restrict__ dlam) {
    __shared__ float red[8];
    int b = blockIdx.x, tid = threadIdx.x;
    int L = d_len[b];
    float lam = log1pf(expf(dlam[0]));
    float lmax = -1e30f;
    for (int s = tid; s < SEQ; s += 256) {
        if (s < L) {
            float xq = d_xq[b * SEQ + s];
            float l = fminf(xq, 0.0f) * 0.03125f - lam * (float)(L - 1 - s);
            lmax = fmaxf(lmax, l);
        }
    }
    lmax = blk_reduce(lmax, red, true);
    float thr = lmax - MARGIN;
    for (int s = tid; s < SEQ; s += 256) {
        int t = b * SEQ + s;
        d_dec[t] = -1e30f;
        if (s < L) {
            float xq = d_xq[t];
            float u = fmaxf(xq, 0.0f) * 0.03125f - lam * (float)(L - 1 - s);
            if (u >= thr) { int p = atomicAdd(&d_cnt, 1); d_idx[p] = t; }
        }
    }
}

// ---------------- K5: gathered GEMM  H = GELU(X[sel] @ W1 + b1) ----------------
// BM=32 x BN=64 tile, BK=16, 128 threads, 4x4 microtile, persistent-stride over m.
#define BM 32
#define BN 64
#define BK 16
__global__ __launch_bounds__(128) void k_gemm(const float* __restrict__ X,
                                              const float* __restrict__ W1,
                                              const float* __restrict__ b1) {
    int cnt = d_cnt;
    int n0 = blockIdx.y * BN;
    __shared__ float Xs[BK][BM];
    __shared__ float Ws[BK][BN];
    __shared__ int tok[BM];
    int tid = threadIdx.x;
    int lxm = tid >> 2, lxk = (tid & 3) << 2;   // X tile: 32 rows x 16 cols, 1 float4/thr
    int wr  = tid >> 3, wc  = (tid & 7) << 3;   // W tile: 16 rows x 64 cols, 2 float4/thr
    int tm  = tid >> 4, tn  = tid & 15;         // 8x16 thread grid, 4x4 micro

    for (int row0 = blockIdx.x * BM; row0 < cnt; row0 += gridDim.x * BM) {
        __syncthreads();
        if (tid < BM) { int r = row0 + tid; tok[tid] = d_idx[(r < cnt) ? r : cnt - 1]; }
        __syncthreads();
        const float* xr = X + (size_t)tok[lxm] * DIM + lxk;

        float acc[4][4];
        #pragma unroll
        for (int i = 0; i < 4; i++)
            #pragma unroll
            for (int j = 0; j < 4; j++) acc[i][j] = 0.0f;

        for (int k0 = 0; k0 < DIM; k0 += BK) {
            float4 v = *(const float4*)(xr + k0);
            const float* wp = W1 + (size_t)(k0 + wr) * HID + n0 + wc;
            float4 w0 = *(const float4*)wp;
            float4 w1 = *(const float4*)(wp + 4);
            Xs[lxk + 0][lxm] = v.x; Xs[lxk + 1][lxm] = v.y;
            Xs[lxk + 2][lxm] = v.z; Xs[lxk + 3][lxm] = v.w;
            *(float4*)&Ws[wr][wc]     = w0;
            *(float4*)&Ws[wr][wc + 4] = w1;
            __syncthreads();
            #pragma unroll
            for (int k = 0; k < BK; k++) {
                float a[4], bb[4];
                *(float4*)a  = *(const float4*)&Xs[k][tm * 4];
                *(float4*)bb = *(const float4*)&Ws[k][tn * 4];
                #pragma unroll
                for (int i = 0; i < 4; i++)
                    #pragma unroll
                    for (int j = 0; j < 4; j++) acc[i][j] += a[i] * bb[j];
            }
            __syncthreads();
        }
        float bv[4];
        *(float4*)bv = *(const float4*)(b1 + n0 + tn * 4);
        #pragma unroll
        for (int i = 0; i < 4; i++) {
            int r = row0 + tm * 4 + i;
            if (r < cnt) {
                float o[4];
                #pragma unroll
                for (int j = 0; j < 4; j++) {
                    float h = acc[i][j] + bv[j];
                    o[j] = 0.5f * h * (1.0f + erff(h * 0.70710678118654752f));
                }
                *(float4*)&d_H[(size_t)r * HID + n0 + tn * 4] = *(float4*)o;
            }
        }
    }
}

// ---------------- K6: gate + decayed logit for selected tokens ----------------
__global__ void k_gate(const float* __restrict__ w2, const float* __restrict__ b2,
                       const float* __restrict__ dlam) {
    int cnt = d_cnt;
    int lane = threadIdx.x & 31;
    for (int i = blockIdx.x * 8 + (threadIdx.x >> 5); i < cnt; i += gridDim.x * 8) {
        int t = d_idx[i];
        const float* h = d_H + (size_t)i * HID;
        float z = 0.0f;
        #pragma unroll
        for (int q2 = 0; q2 < 4; q2++) {
            float4 a = *(const float4*)(h + lane * 4 + q2 * 128);
            float4 b = *(const float4*)(w2 + lane * 4 + q2 * 128);
            z += a.x * b.x + a.y * b.y + a.z * b.z + a.w * b.w;
        }
        #pragma unroll
        for (int o = 16; o; o >>= 1) z += __shfl_xor_sync(0xffffffffu, z, o);
        if (lane == 0) {
            float g = 1.0f / (1.0f + expf(-(z + b2[0])));
            d_g[t] = g;
            int b = t >> 11, s = t & (SEQ - 1);
            int L = d_len[b];
            float lam = log1pf(expf(dlam[0]));
            d_dec[t] = g * d_xq[t] * 0.03125f - lam * (float)(L - 1 - s);
        }
    }
}

// ---------------- K7: row softmax -> w = alpha * g ----------------
__global__ void k_softmax() {
    __shared__ float red[8];
    int b = blockIdx.x, tid = threadIdx.x;
    float v[8];
    float mx = -1e30f;
    #pragma unroll
    for (int q2 = 0; q2 < 8; q2++) {
        v[q2] = d_dec[b * SEQ + tid + q2 * 256];
        mx = fmaxf(mx, v[q2]);
    }
    mx = blk_reduce(mx, red, true);
    float p[8];
    float sm = 0.0f;
    #pragma unroll
    for (int q2 = 0; q2 < 8; q2++) {
        p[q2] = (v[q2] > -1e29f) ? expf(v[q2] - mx) : 0.0f;
        sm += p[q2];
    }
    sm = blk_reduce(sm, red, false);
    float inv = 1.0f / sm;
    #pragma unroll
    for (int q2 = 0; q2 < 8; q2++) {
        int t = b * SEQ + tid + q2 * 256;
        d_w[t] = (p[q2] > 0.0f) ? p[q2] * inv * d_g[t] : 0.0f;
    }
}

// ---------------- K8: scene[b,d] = sum_s w[b,s] * x[b,s,d] (skip zero prefix) --------
__global__ void k_scene(const float* __restrict__ X, float* __restrict__ out) {
    int b = blockIdx.y;
    int d = blockIdx.x * 128 + threadIdx.x;
    __shared__ float w[SEQ];
    __shared__ int slo_s;
    int L = d_len[b];
    if (threadIdx.x == 0) slo_s = L;
    __syncthreads();
    int slo = L;
    for (int s = threadIdx.x; s < SEQ; s += 128) {
        float wv = d_w[b * SEQ + s];
        w[s] = wv;
        if (wv != 0.0f && s < slo) slo = s;
    }
    atomicMin(&slo_s, slo);
    __syncthreads();
    const float* xb = X + (size_t)b * SEQ * DIM + d;
    float a0 = 0.0f, a1 = 0.0f, a2 = 0.0f, a3 = 0.0f;
    int s = slo_s;
    for (; s + 3 < L; s += 4) {
        a0 += w[s + 0] * xb[(size_t)(s + 0) * DIM];
        a1 += w[s + 1] * xb[(size_t)(s + 1) * DIM];
        a2 += w[s + 2] * xb[(size_t)(s + 2) * DIM];
        a3 += w[s + 3] * xb[(size_t)(s + 3) * DIM];
    }
    for (; s < L; s++) a0 += w[s] * xb[(size_t)s * DIM];
    out[b * DIM + d] = (a0 + a1) + (a2 + a3);
}

// ---------------- launch ----------------
extern "C" void kernel_launch(void* const* d_in, const int* in_sizes, int n_in,
                              void* d_out, int out_size) {
    (void)in_sizes; (void)n_in; (void)out_size;
    const float* X    = (const float*)d_in[0];
    const void*  mask = d_in[1];
    const float* gw1  = (const float*)d_in[2];
    const float* gb1  = (const float*)d_in[3];
    const float* gw2  = (const float*)d_in[4];
    const float* gb2  = (const float*)d_in[5];
    const float* dlam = (const float*)d_in[6];
    const float* q    = (const float*)d_in[7];
    const float* kw   = (const float*)d_in[8];
    // d_in[9] = key_b: constant softmax shift, provably drops out
    float* out = (float*)d_out;

    k_detect  <<<1, 256>>>((const unsigned char*)mask);
    k_len     <<<BNUM, 256>>>(mask);
    k_qk      <<<DIM, 256>>>(kw, q);
    k_xq      <<<NTOK / 16, 256>>>(X);
    k_select  <<<BNUM, 256>>>(dlam);
    k_gemm    <<<dim3(256, HID / BN), 128>>>(X, gw1, gb1);
    k_gate    <<<512, 256>>>(gw2, gb2, dlam);
    k_softmax <<<BNUM, 256>>>();
    k_scene   <<<dim3(DIM / 128, BNUM), 128>>>(X, out);
}

// round 7
// speedup vs baseline: 2.1694x; 1.9317x over previous
#include <cuda_runtime.h>
#include <math.h>

#define BNUM 32
#define SEQ  2048
#define DIM  1024
#define HID  512
#define NTOK (BNUM * SEQ)   // 65536
#define MARGIN 20.0f        // dropped alpha mass < 2048*exp(-20) ~ 4e-6 << 1e-3 tol

// ---------------- scratch (alignment under our control) ----------------
__device__ __align__(256) float d_H[(size_t)NTOK * HID];
__device__ __align__(256) float d_qk[DIM];
__device__ float d_xq[NTOK];
__device__ float d_g[NTOK];
__device__ float d_dec[NTOK];
__device__ int   d_len[BNUM];
__device__ int   d_idx[NTOK];
__device__ int   d_cnt;
__device__ int   d_c0a[16];
__device__ int   d_c3a[16];

// ---------------- reduce helpers ----------------
__device__ __forceinline__ float warp_red(float v, bool domax) {
    #pragma unroll
    for (int o = 16; o; o >>= 1) {
        float ov = __shfl_xor_sync(0xffffffffu, v, o);
        v = domax ? fmaxf(v, ov) : (v + ov);
    }
    return v;
}
__device__ __forceinline__ float blk_reduce256(float v, float* red, bool domax) {
    v = warp_red(v, domax);
    int w = threadIdx.x >> 5;
    if ((threadIdx.x & 31) == 0) red[w] = v;
    __syncthreads();
    float r = (threadIdx.x < 8) ? red[threadIdx.x] : (domax ? -1e30f : 0.0f);
    if (threadIdx.x < 32) {
        #pragma unroll
        for (int o = 4; o; o >>= 1) {
            float orr = __shfl_xor_sync(0xffffffffu, r, o);
            r = domax ? fmaxf(r, orr) : (r + orr);
        }
        if (threadIdx.x == 0) red[0] = r;
    }
    __syncthreads();
    float out = red[0];
    __syncthreads();
    return out;
}
__device__ __forceinline__ float blk_reduce128(float v, float* red, bool domax) {
    v = warp_red(v, domax);
    int w = threadIdx.x >> 5;
    if ((threadIdx.x & 31) == 0) red[w] = v;
    __syncthreads();
    if (threadIdx.x < 32) {
        float r = (threadIdx.x < 4) ? red[threadIdx.x] : (domax ? -1e30f : 0.0f);
        #pragma unroll
        for (int o = 2; o; o >>= 1) {
            float orr = __shfl_xor_sync(0xffffffffu, r, o);
            r = domax ? fmaxf(r, orr) : (r + orr);
        }
        if (threadIdx.x == 0) red[0] = r;
    }
    __syncthreads();
    float out = red[0];
    __syncthreads();
    return out;
}

// ---------------- kA: blocks 0..15 = detect (byte loads), 16.. = qk (scalar) ---------
// Detect reads first 65536 bytes bytewise (in-bounds for u8/i32/f32 mask).
// i32 0/1 LE: nonzero bytes only at p%4==0. f32 1.0f LE: only p%4 in {2,3}. u8: mixed.
__global__ void kA(const unsigned char* __restrict__ mb,
                   const float* __restrict__ kw, const float* __restrict__ q) {
    int tid = threadIdx.x;
    if (blockIdx.x < 16) {
        __shared__ int c0s, c3s;
        if (tid == 0) { c0s = 0; c3s = 0; if (blockIdx.x == 0) d_cnt = 0; }
        __syncthreads();
        const unsigned char* p = mb + blockIdx.x * 4096 + tid * 16;
        int c0 = 0, c3 = 0;
        #pragma unroll
        for (int i = 0; i < 16; i++) {
            unsigned char v = p[i];
            int pos = (tid * 16 + i) & 3;
            if (v) { if (pos == 0) c0++; else if (pos == 3) c3++; }
        }
        #pragma unroll
        for (int o = 16; o; o >>= 1) {
            c0 += __shfl_xor_sync(0xffffffffu, c0, o);
            c3 += __shfl_xor_sync(0xffffffffu, c3, o);
        }
        if ((tid & 31) == 0) { atomicAdd(&c0s, c0); atomicAdd(&c3s, c3); }
        __syncthreads();
        if (tid == 0) { d_c0a[blockIdx.x] = c0s; d_c3a[blockIdx.x] = c3s; }
    } else {
        __shared__ float red[8];
        int d = blockIdx.x - 16;
        const float* row = kw + (size_t)d * DIM;
        float s = 0.0f;
        #pragma unroll
        for (int i = 0; i < 4; i++) {          // scalar, warp-contiguous
            int e = tid + i * 256;
            s += row[e] * q[e];
        }
        s = blk_reduce256(s, red, false);
        if (tid == 0) d_qk[d] = s;
    }
}

// dtype decision from detect partials: 0=u8, 1=int32, 2=float32
__device__ __forceinline__ int mask_dtype() {
    int c0 = 0, c3 = 0;
    #pragma unroll
    for (int i = 0; i < 16; i++) { c0 += d_c0a[i]; c3 += d_c3a[i]; }
    if (c0 > 0 && c3 == 0) return 1;
    if (c0 == 0 && c3 > 0) return 2;
    return 0;
}

// ---------------- kB: blocks 0..31 = len, blocks 32.. = xq (scalar loads) ------------
__global__ void kB(const void* __restrict__ mask, const float* __restrict__ X) {
    int tid = threadIdx.x;
    if (blockIdx.x < 32) {
        int b = blockIdx.x;
        __shared__ int cs;
        if (tid == 0) cs = 0;
        __syncthreads();
        int c = 0, f = mask_dtype();
        if (f == 0) {
            const unsigned char* m = (const unsigned char*)mask + b * SEQ;
            #pragma unroll
            for (int i = 0; i < 8; i++) c += (m[tid + i * 256] != 0);
        } else {
            // i32/f32 buffer: element loads (4B) on a naturally 4-aligned buffer
            const unsigned int* m = (const unsigned int*)mask + b * SEQ;
            #pragma unroll
            for (int i = 0; i < 8; i++) c += (m[tid + i * 256] != 0u);
        }
        atomicAdd(&cs, c);
        __syncthreads();
        if (tid == 0) d_len[b] = SEQ - cs;
    } else {
        __shared__ float qs[DIM];
        for (int i = tid; i < DIM; i += 256) qs[i] = d_qk[i];
        __syncthreads();
        int w = tid >> 5, lane = tid & 31;
        int t0 = (blockIdx.x - 32) * 16 + w;      // warp handles t0 and t0+8
        const float* x0 = X + (size_t)t0 * DIM;
        const float* x1 = x0 + (size_t)8 * DIM;
        float s0 = 0.0f, s1 = 0.0f;
        #pragma unroll
        for (int i = 0; i < 32; i++) {            // scalar, warp-contiguous per instr
            int e = lane + i * 32;
            float bq = qs[e];
            s0 += x0[e] * bq;
            s1 += x1[e] * bq;
        }
        s0 = warp_red(s0, false);
        s1 = warp_red(s1, false);
        if (lane == 0) { d_xq[t0] = s0; d_xq[t0 + 8] = s1; }
    }
}

// ---------------- kC: rigorous-bound token selection ----------------
// g in (0,1) => g*xq in [min(xq,0), max(xq,0)]. Select s iff upper >= max lower - MARGIN.
__global__ void kC(const float* __restrict__ dlam) {
    __shared__ float red[8];
    int b = blockIdx.x, tid = threadIdx.x;
    int L = d_len[b];
    float lam = log1pf(expf(dlam[0]));
    float lmax = -1e30f;
    for (int s = tid; s < SEQ; s += 256) {
        if (s < L) {
            float xq = d_xq[b * SEQ + s];
            float l = fminf(xq, 0.0f) * 0.03125f - lam * (float)(L - 1 - s);
            lmax = fmaxf(lmax, l);
        }
    }
    lmax = blk_reduce256(lmax, red, true);
    float thr = lmax - MARGIN;
    for (int s = tid; s < SEQ; s += 256) {
        int t = b * SEQ + s;
        d_dec[t] = -1e30f;
        if (s < L) {
            float xq = d_xq[t];
            float u = fmaxf(xq, 0.0f) * 0.03125f - lam * (float)(L - 1 - s);
            if (u >= thr) { int p = atomicAdd(&d_cnt, 1); d_idx[p] = t; }
        }
    }
}

// ---------------- kD: gathered GEMM  H = GELU(X[sel] @ W1 + b1) ----------------
#define BM 32
#define BN 64
#define BK 16
__global__ __launch_bounds__(128) void kD(const float* __restrict__ X,
                                          const float* __restrict__ W1,
                                          const float* __restrict__ b1) {
    int cnt = d_cnt;
    int n0 = blockIdx.y * BN;
    __shared__ float Xs[BK][BM];
    __shared__ float Ws[BK][BN];
    __shared__ int tok[BM];
    int tid = threadIdx.x;
    int lxm = tid >> 2, lxk = (tid & 3) << 2;
    int wr  = tid >> 3, wc  = (tid & 7) << 3;
    int tm  = tid >> 4, tn  = tid & 15;

    for (int row0 = blockIdx.x * BM; row0 < cnt; row0 += gridDim.x * BM) {
        __syncthreads();
        if (tid < BM) { int r = row0 + tid; tok[tid] = d_idx[(r < cnt) ? r : cnt - 1]; }
        __syncthreads();
        const float* xr = X + (size_t)tok[lxm] * DIM + lxk;

        float acc[4][4];
        #pragma unroll
        for (int i = 0; i < 4; i++)
            #pragma unroll
            for (int j = 0; j < 4; j++) acc[i][j] = 0.0f;

        for (int k0 = 0; k0 < DIM; k0 += BK) {
            // scalar global loads (no alignment assumption on inputs)
            #pragma unroll
            for (int c = 0; c < 4; c++) Xs[lxk + c][lxm] = xr[k0 + c];
            const float* wp = W1 + (size_t)(k0 + wr) * HID + n0 + wc;
            #pragma unroll
            for (int c = 0; c < 8; c++) Ws[wr][wc + c] = wp[c];
            __syncthreads();
            #pragma unroll
            for (int k = 0; k < BK; k++) {
                float a[4], bb[4];
                *(float4*)a  = *(const float4*)&Xs[k][tm * 4];   // smem: aligned
                *(float4*)bb = *(const float4*)&Ws[k][tn * 4];
                #pragma unroll
                for (int i = 0; i < 4; i++)
                    #pragma unroll
                    for (int j = 0; j < 4; j++) acc[i][j] += a[i] * bb[j];
            }
            __syncthreads();
        }
        #pragma unroll
        for (int i = 0; i < 4; i++) {
            int r = row0 + tm * 4 + i;
            if (r < cnt) {
                float o[4];
                #pragma unroll
                for (int j = 0; j < 4; j++) {
                    float h = acc[i][j] + b1[n0 + tn * 4 + j];
                    o[j] = 0.5f * h * (1.0f + erff(h * 0.70710678118654752f));
                }
                *(float4*)&d_H[(size_t)r * HID + n0 + tn * 4] = *(float4*)o;  // own scratch
            }
        }
    }
}

// ---------------- kE: gate + decayed logit for selected tokens ----------------
__global__ void kE(const float* __restrict__ w2, const float* __restrict__ b2,
                   const float* __restrict__ dlam) {
    int cnt = d_cnt;
    int lane = threadIdx.x & 31;
    for (int i = blockIdx.x * 8 + (threadIdx.x >> 5); i < cnt; i += gridDim.x * 8) {
        int t = d_idx[i];
        const float* h = d_H + (size_t)i * HID;
        float z = 0.0f;
        #pragma unroll
        for (int j = 0; j < 16; j++) {          // scalar, warp-contiguous
            int e = lane + j * 32;
            z += h[e] * w2[e];
        }
        z = warp_red(z, false);
        if (lane == 0) {
            float g = 1.0f / (1.0f + expf(-(z + b2[0])));
            d_g[t] = g;
            int b = t >> 11, s = t & (SEQ - 1);
            int L = d_len[b];
            float lam = log1pf(expf(dlam[0]));
            d_dec[t] = g * d_xq[t] * 0.03125f - lam * (float)(L - 1 - s);
        }
    }
}

// ---------------- kF: fused softmax + scene pooling ----------------
// grid (DIM/128, BNUM), 128 threads. Each block recomputes the row softmax
// (deterministic, identical across the 8 d-chunks) then does its weighted sum.
__global__ __launch_bounds__(128) void kF(const float* __restrict__ X,
                                          float* __restrict__ out) {
    __shared__ float w[SEQ];
    __shared__ float red[4];
    __shared__ int slo_s;
    int b = blockIdx.y;
    int tid = threadIdx.x;
    int L = d_len[b];
    if (tid == 0) slo_s = L;

    float v[16];
    float mx = -1e30f;
    #pragma unroll
    for (int i = 0; i < 16; i++) {
        v[i] = d_dec[b * SEQ + tid + i * 128];
        mx = fmaxf(mx, v[i]);
    }
    mx = blk_reduce128(mx, red, true);
    float p[16];
    float sm = 0.0f;
    #pragma unroll
    for (int i = 0; i < 16; i++) {
        p[i] = (v[i] > -1e29f) ? expf(v[i] - mx) : 0.0f;
        sm += p[i];
    }
    sm = blk_reduce128(sm, red, false);
    float inv = 1.0f / sm;
    int slo = L;
    #pragma unroll
    for (int i = 0; i < 16; i++) {
        int s = tid + i * 128;
        float wv = (p[i] > 0.0f) ? p[i] * inv * d_g[b * SEQ + s] : 0.0f;
        w[s] = wv;
        if (wv != 0.0f && s < slo) slo = s;
    }
    atomicMin(&slo_s, slo);
    __syncthreads();

    int d = blockIdx.x * 128 + tid;
    const float* xb = X + (size_t)b * SEQ * DIM + d;
    float a0 = 0.0f, a1 = 0.0f, a2 = 0.0f, a3 = 0.0f;
    int s = slo_s;
    for (; s + 3 < L; s += 4) {
        a0 += w[s + 0] * xb[(size_t)(s + 0) * DIM];
        a1 += w[s + 1] * xb[(size_t)(s + 1) * DIM];
        a2 += w[s + 2] * xb[(size_t)(s + 2) * DIM];
        a3 += w[s + 3] * xb[(size_t)(s + 3) * DIM];
    }
    for (; s < L; s++) a0 += w[s] * xb[(size_t)s * DIM];
    out[b * DIM + d] = (a0 + a1) + (a2 + a3);
}

// ---------------- launch ----------------
extern "C" void kernel_launch(void* const* d_in, const int* in_sizes, int n_in,
                              void* d_out, int out_size) {
    (void)in_sizes; (void)n_in; (void)out_size;
    const float* X    = (const float*)d_in[0];
    const void*  mask = d_in[1];
    const float* gw1  = (const float*)d_in[2];
    const float* gb1  = (const float*)d_in[3];
    const float* gw2  = (const float*)d_in[4];
    const float* gb2  = (const float*)d_in[5];
    const float* dlam = (const float*)d_in[6];
    const float* q    = (const float*)d_in[7];
    const float* kw   = (const float*)d_in[8];
    // d_in[9] = key_b: constant softmax shift, provably drops out
    float* out = (float*)d_out;

    kA<<<16 + DIM, 256>>>((const unsigned char*)mask, kw, q);
    kB<<<32 + NTOK / 16, 256>>>(mask, X);
    kC<<<BNUM, 256>>>(dlam);
    kD<<<dim3(64, HID / BN), 128>>>(X, gw1, gb1);
    kE<<<128, 256>>>(gw2, gb2, dlam);
    kF<<<dim3(DIM / 128, BNUM), 128>>>(X, out);
}

// round 10
// speedup vs baseline: 2.2600x; 1.0417x over previous
#include <cuda_runtime.h>
#include <math.h>

#define BNUM 32
#define SEQ  2048
#define DIM  1024
#define HID  512
#define NTOK (BNUM * SEQ)   // 65536
#define MARGIN 20.0f        // dropped alpha mass < 2048*exp(-20) ~ 4e-6 << 1e-3 tol

// ---------------- scratch (alignment under our control) ----------------
__device__ __align__(256) float d_H[(size_t)NTOK * HID];
__device__ __align__(256) float d_qk[DIM];
__device__ float d_xq[NTOK];
__device__ float d_g[NTOK];
__device__ float d_dec[NTOK];
__device__ int   d_len[BNUM];
__device__ int   d_idx[NTOK];
__device__ int   d_cnt;
__device__ int   d_c0a[16];
__device__ int   d_c3a[16];

// ---------------- reduce helpers ----------------
__device__ __forceinline__ float warp_red(float v, bool domax) {
    #pragma unroll
    for (int o = 16; o; o >>= 1) {
        float ov = __shfl_xor_sync(0xffffffffu, v, o);
        v = domax ? fmaxf(v, ov) : (v + ov);
    }
    return v;
}
__device__ __forceinline__ float blk_reduce256(float v, float* red, bool domax) {
    v = warp_red(v, domax);
    int w = threadIdx.x >> 5;
    if ((threadIdx.x & 31) == 0) red[w] = v;
    __syncthreads();
    float r = (threadIdx.x < 8) ? red[threadIdx.x] : (domax ? -1e30f : 0.0f);
    if (threadIdx.x < 32) {
        #pragma unroll
        for (int o = 4; o; o >>= 1) {
            float orr = __shfl_xor_sync(0xffffffffu, r, o);
            r = domax ? fmaxf(r, orr) : (r + orr);
        }
        if (threadIdx.x == 0) red[0] = r;
    }
    __syncthreads();
    float out = red[0];
    __syncthreads();
    return out;
}
__device__ __forceinline__ float blk_reduce128(float v, float* red, bool domax) {
    v = warp_red(v, domax);
    int w = threadIdx.x >> 5;
    if ((threadIdx.x & 31) == 0) red[w] = v;
    __syncthreads();
    if (threadIdx.x < 32) {
        float r = (threadIdx.x < 4) ? red[threadIdx.x] : (domax ? -1e30f : 0.0f);
        #pragma unroll
        for (int o = 2; o; o >>= 1) {
            float orr = __shfl_xor_sync(0xffffffffu, r, o);
            r = domax ? fmaxf(r, orr) : (r + orr);
        }
        if (threadIdx.x == 0) red[0] = r;
    }
    __syncthreads();
    float out = red[0];
    __syncthreads();
    return out;
}

// ---------------- k0d: mask dtype detect (16 blocks, byte loads) ----------------
// Reads first 65536 bytes bytewise (in-bounds for u8/i32/f32 mask).
// i32 0/1 LE: nonzero bytes only at p%4==0. f32 1.0f LE: only p%4 in {2,3}. u8: mixed.
__global__ void k0d(const unsigned char* __restrict__ mb) {
    int tid = threadIdx.x;
    __shared__ int c0s, c3s;
    if (tid == 0) { c0s = 0; c3s = 0; if (blockIdx.x == 0) d_cnt = 0; }
    __syncthreads();
    const unsigned char* p = mb + blockIdx.x * 4096 + tid * 16;
    int c0 = 0, c3 = 0;
    #pragma unroll
    for (int i = 0; i < 16; i++) {
        unsigned char v = p[i];
        int pos = (tid * 16 + i) & 3;
        if (v) { if (pos == 0) c0++; else if (pos == 3) c3++; }
    }
    #pragma unroll
    for (int o = 16; o; o >>= 1) {
        c0 += __shfl_xor_sync(0xffffffffu, c0, o);
        c3 += __shfl_xor_sync(0xffffffffu, c3, o);
    }
    if ((tid & 31) == 0) { atomicAdd(&c0s, c0); atomicAdd(&c3s, c3); }
    __syncthreads();
    if (tid == 0) { d_c0a[blockIdx.x] = c0s; d_c3a[blockIdx.x] = c3s; }
}

// dtype decision from detect partials: 0=u8, 1=int32, 2=float32
__device__ __forceinline__ int mask_dtype() {
    int c0 = 0, c3 = 0;
    #pragma unroll
    for (int i = 0; i < 16; i++) { c0 += d_c0a[i]; c3 += d_c3a[i]; }
    if (c0 > 0 && c3 == 0) return 1;
    if (c0 == 0 && c3 > 0) return 2;
    return 0;
}

// ---------------- kA: blocks 0..31 = len, blocks 32.. = qk (scalar loads) ------------
__global__ void kA(const void* __restrict__ mask,
                   const float* __restrict__ kw, const float* __restrict__ q) {
    int tid = threadIdx.x;
    if (blockIdx.x < 32) {
        int b = blockIdx.x;
        __shared__ int cs;
        if (tid == 0) cs = 0;
        __syncthreads();
        int c = 0, f = mask_dtype();
        if (f == 0) {
            const unsigned char* m = (const unsigned char*)mask + b * SEQ;
            #pragma unroll
            for (int i = 0; i < 8; i++) c += (m[tid + i * 256] != 0);
        } else {
            const unsigned int* m = (const unsigned int*)mask + b * SEQ;
            #pragma unroll
            for (int i = 0; i < 8; i++) c += (m[tid + i * 256] != 0u);
        }
        atomicAdd(&cs, c);
        __syncthreads();
        if (tid == 0) d_len[b] = SEQ - cs;
    } else {
        __shared__ float red[8];
        int d = blockIdx.x - 32;
        const float* row = kw + (size_t)d * DIM;
        float s = 0.0f;
        #pragma unroll
        for (int i = 0; i < 4; i++) {          // scalar, warp-contiguous
            int e = tid + i * 256;
            s += row[e] * q[e];
        }
        s = blk_reduce256(s, red, false);
        if (tid == 0) d_qk[d] = s;
    }
}

// ---------------- kB: xq for valid tokens only (padding blocks exit early) -----------
__global__ void kB(const float* __restrict__ X) {
    int blk = blockIdx.x;                 // 4096 blocks, 16 tokens each
    int b = blk >> 7;                     // 128 blocks per batch row
    int s_start = (blk & 127) << 4;
    if (s_start >= d_len[b]) return;      // fully-padded block: xq never read
    int tid = threadIdx.x;
    __shared__ float qs[DIM];
    for (int i = tid; i < DIM; i += 256) qs[i] = d_qk[i];
    __syncthreads();
    int w = tid >> 5, lane = tid & 31;
    int t0 = blk * 16 + w;                // warp handles t0 and t0+8
    const float* x0 = X + (size_t)t0 * DIM;
    const float* x1 = x0 + (size_t)8 * DIM;
    float s0 = 0.0f, s1 = 0.0f;
    #pragma unroll
    for (int i = 0; i < 32; i++) {        // scalar, warp-contiguous per instr
        int e = lane + i * 32;
        float bq = qs[e];
        s0 += x0[e] * bq;
        s1 += x1[e] * bq;
    }
    s0 = warp_red(s0, false);
    s1 = warp_red(s1, false);
    if (lane == 0) { d_xq[t0] = s0; d_xq[t0 + 8] = s1; }
}

// ---------------- kC: rigorous-bound token selection ----------------
// g in (0,1) => g*xq in [min(xq,0), max(xq,0)]. Select s iff upper >= max lower - MARGIN.
__global__ void kC(const float* __restrict__ dlam) {
    __shared__ float red[8];
    int b = blockIdx.x, tid = threadIdx.x;
    int L = d_len[b];
    float lam = log1pf(expf(dlam[0]));
    float lmax = -1e30f;
    for (int s = tid; s < SEQ; s += 256) {
        if (s < L) {
            float xq = d_xq[b * SEQ + s];
            float l = fminf(xq, 0.0f) * 0.03125f - lam * (float)(L - 1 - s);
            lmax = fmaxf(lmax, l);
        }
    }
    lmax = blk_reduce256(lmax, red, true);
    float thr = lmax - MARGIN;
    for (int s = tid; s < SEQ; s += 256) {
        int t = b * SEQ + s;
        d_dec[t] = -1e30f;
        if (s < L) {
            float xq = d_xq[t];
            float u = fmaxf(xq, 0.0f) * 0.03125f - lam * (float)(L - 1 - s);
            if (u >= thr) { int p = atomicAdd(&d_cnt, 1); d_idx[p] = t; }
        }
    }
}

// ---------------- kD: gathered GEMM  H = GELU(X[sel] @ W1 + b1) ----------------
// Double-buffered smem pipeline: registers prefetch tile k+1 during compute of k.
#define BM 32
#define BN 64
#define BK 16
__global__ __launch_bounds__(128) void kD(const float* __restrict__ X,
                                          const float* __restrict__ W1,
                                          const float* __restrict__ b1) {
    int cnt = d_cnt;
    int n0 = blockIdx.y * BN;
    __shared__ float Xs[2][BK][BM];
    __shared__ float Ws[2][BK][BN];
    __shared__ int tok[BM];
    int tid = threadIdx.x;
    int lxm = tid >> 2, lxk = (tid & 3) << 2;   // X tile loader: row lxm, cols lxk..+3
    int wr  = tid >> 3, wc  = (tid & 7) << 3;   // W tile loader: row wr, cols wc..+7
    int tm  = tid >> 4, tn  = tid & 15;         // 8x16 thread grid, 4x4 micro

    for (int row0 = blockIdx.x * BM; row0 < cnt; row0 += gridDim.x * BM) {
        __syncthreads();   // all compute on previous row0's smem finished
        if (tid < BM) { int r = row0 + tid; tok[tid] = d_idx[(r < cnt) ? r : cnt - 1]; }
        __syncthreads();
        const float* xr = X + (size_t)tok[lxm] * DIM + lxk;

        float acc[4][4];
        #pragma unroll
        for (int i = 0; i < 4; i++)
            #pragma unroll
            for (int j = 0; j < 4; j++) acc[i][j] = 0.0f;

        float xv[4], wv[8];
        // preload k0 = 0 (scalar loads: no input-alignment assumption)
        #pragma unroll
        for (int c = 0; c < 4; c++) xv[c] = xr[c];
        {
            const float* wp = W1 + (size_t)wr * HID + n0 + wc;
            #pragma unroll
            for (int c = 0; c < 8; c++) wv[c] = wp[c];
        }
        #pragma unroll
        for (int c = 0; c < 4; c++) Xs[0][lxk + c][lxm] = xv[c];
        #pragma unroll
        for (int c = 0; c < 8; c++) Ws[0][wr][wc + c] = wv[c];
        __syncthreads();

        int buf = 0;
        for (int k0 = 0; k0 < DIM; k0 += BK) {
            bool has_next = (k0 + BK) < DIM;
            if (has_next) {
                // issue next tile's LDGs; latency overlaps the FMA block below
                #pragma unroll
                for (int c = 0; c < 4; c++) xv[c] = xr[k0 + BK + c];
                const float* wp = W1 + (size_t)(k0 + BK + wr) * HID + n0 + wc;
                #pragma unroll
                for (int c = 0; c < 8; c++) wv[c] = wp[c];
            }
            #pragma unroll
            for (int k = 0; k < BK; k++) {
                float a[4], bb[4];
                *(float4*)a  = *(const float4*)&Xs[buf][k][tm * 4];   // smem: aligned
                *(float4*)bb = *(const float4*)&Ws[buf][k][tn * 4];
                #pragma unroll
                for (int i = 0; i < 4; i++)
                    #pragma unroll
                    for (int j = 0; j < 4; j++) acc[i][j] += a[i] * bb[j];
            }
            if (has_next) {
                #pragma unroll
                for (int c = 0; c < 4; c++) Xs[buf ^ 1][lxk + c][lxm] = xv[c];
                #pragma unroll
                for (int c = 0; c < 8; c++) Ws[buf ^ 1][wr][wc + c] = wv[c];
                __syncthreads();
                buf ^= 1;
            }
        }
        #pragma unroll
        for (int i = 0; i < 4; i++) {
            int r = row0 + tm * 4 + i;
            if (r < cnt) {
                float o[4];
                #pragma unroll
                for (int j = 0; j < 4; j++) {
                    float h = acc[i][j] + b1[n0 + tn * 4 + j];
                    o[j] = 0.5f * h * (1.0f + erff(h * 0.70710678118654752f));
                }
                *(float4*)&d_H[(size_t)r * HID + n0 + tn * 4] = *(float4*)o;  // own scratch
            }
        }
    }
}

// ---------------- kE: gate + decayed logit for selected tokens ----------------
__global__ void kE(const float* __restrict__ w2, const float* __restrict__ b2,
                   const float* __restrict__ dlam) {
    int cnt = d_cnt;
    int lane = threadIdx.x & 31;
    for (int i = blockIdx.x * 8 + (threadIdx.x >> 5); i < cnt; i += gridDim.x * 8) {
        int t = d_idx[i];
        const float* h = d_H + (size_t)i * HID;
        float z = 0.0f;
        #pragma unroll
        for (int j = 0; j < 16; j++) {          // scalar, warp-contiguous
            int e = lane + j * 32;
            z += h[e] * w2[e];
        }
        z = warp_red(z, false);
        if (lane == 0) {
            float g = 1.0f / (1.0f + expf(-(z + b2[0])));
            d_g[t] = g;
            int b = t >> 11, s = t & (SEQ - 1);
            int L = d_len[b];
            float lam = log1pf(expf(dlam[0]));
            d_dec[t] = g * d_xq[t] * 0.03125f - lam * (float)(L - 1 - s);
        }
    }
}

// ---------------- kF: fused softmax + scene pooling ----------------
// grid (DIM/128, BNUM), 128 threads. Each block recomputes the row softmax
// (deterministic, identical across the 8 d-chunks) then does its weighted sum.
__global__ __launch_bounds__(128) void kF(const float* __restrict__ X,
                                          float* __restrict__ out) {
    __shared__ float w[SEQ];
    __shared__ float red[4];
    __shared__ int slo_s;
    int b = blockIdx.y;
    int tid = threadIdx.x;
    int L = d_len[b];
    if (tid == 0) slo_s = L;

    float v[16];
    float mx = -1e30f;
    #pragma unroll
    for (int i = 0; i < 16; i++) {
        v[i] = d_dec[b * SEQ + tid + i * 128];
        mx = fmaxf(mx, v[i]);
    }
    mx = blk_reduce128(mx, red, true);
    float p[16];
    float sm = 0.0f;
    #pragma unroll
    for (int i = 0; i < 16; i++) {
        p[i] = (v[i] > -1e29f) ? expf(v[i] - mx) : 0.0f;
        sm += p[i];
    }
    sm = blk_reduce128(sm, red, false);
    float inv = 1.0f / sm;
    int slo = L;
    #pragma unroll
    for (int i = 0; i < 16; i++) {
        int s = tid + i * 128;
        float wv = (p[i] > 0.0f) ? p[i] * inv * d_g[b * SEQ + s] : 0.0f;
        w[s] = wv;
        if (wv != 0.0f && s < slo) slo = s;
    }
    atomicMin(&slo_s, slo);
    __syncthreads();

    int d = blockIdx.x * 128 + tid;
    const float* xb = X + (size_t)b * SEQ * DIM + d;
    float a0 = 0.0f, a1 = 0.0f, a2 = 0.0f, a3 = 0.0f;
    int s = slo_s;
    for (; s + 3 < L; s += 4) {
        a0 += w[s + 0] * xb[(size_t)(s + 0) * DIM];
        a1 += w[s + 1] * xb[(size_t)(s + 1) * DIM];
        a2 += w[s + 2] * xb[(size_t)(s + 2) * DIM];
        a3 += w[s + 3] * xb[(size_t)(s + 3) * DIM];
    }
    for (; s < L; s++) a0 += w[s] * xb[(size_t)s * DIM];
    out[b * DIM + d] = (a0 + a1) + (a2 + a3);
}

// ---------------- launch ----------------
extern "C" void kernel_launch(void* const* d_in, const int* in_sizes, int n_in,
                              void* d_out, int out_size) {
    (void)in_sizes; (void)n_in; (void)out_size;
    const float* X    = (const float*)d_in[0];
    const void*  mask = d_in[1];
    const float* gw1  = (const float*)d_in[2];
    const float* gb1  = (const float*)d_in[3];
    const float* gw2  = (const float*)d_in[4];
    const float* gb2  = (const float*)d_in[5];
    const float* dlam = (const float*)d_in[6];
    const float* q    = (const float*)d_in[7];
    const float* kw   = (const float*)d_in[8];
    // d_in[9] = key_b: constant softmax shift, provably drops out
    float* out = (float*)d_out;

    k0d<<<16, 256>>>((const unsigned char*)mask);
    kA <<<32 + DIM, 256>>>(mask, kw, q);
    kB <<<NTOK / 16, 256>>>(X);
    kC <<<BNUM, 256>>>(dlam);
    kD <<<dim3(64, HID / BN), 128>>>(X, gw1, gb1);
    kE <<<128, 256>>>(gw2, gb2, dlam);
    kF <<<dim3(DIM / 128, BNUM), 128>>>(X, out);
}